// round 1
// baseline (speedup 1.0000x reference)
#include <cuda_runtime.h>
#include <cstdint>

// MSPushPullLoss: multi-scale discriminative push/pull loss.
// B=16 batches, C=16 instance labels (+0 background), 3 scales.
// Two passes over 22M pixels (8B each): pass1 = per-(b,label) sum/count
// (fixed-point packed u64 shared atomics), pass2 = pull term using means.
// All accumulation is integer fixed-point -> bit-deterministic across replays.

#define NSEG 272                  // 16 batches * 17 (label 0..16)
#define CNT_BITS 21
#define CNT_MASK ((1ll << CNT_BITS) - 1)
#define FPSCALE_F 65536.0f
#define FPSCALE_D 65536.0

__device__ unsigned long long g_bins1[3 * NSEG];  // packed (valsum<<21 | count) per scale
__device__ unsigned long long g_bins2[3 * NSEG];  // pull valsum (fixed point) per scale
__device__ float g_mean[NSEG];                    // pooled per-segment mean

// ---------------------------------------------------------------------------
__global__ void zero_kernel() {
    int t = threadIdx.x;
    if (t < 3 * NSEG) {
        g_bins1[t] = 0ull;
        g_bins2[t] = 0ull;
    }
}

// ---------------------------------------------------------------------------
__device__ __forceinline__ void acc1(unsigned long long* wb, float x, int gv) {
    unsigned lab = (unsigned)(gv - 1);
    if (lab <= 15u) {
        long long q = __float2ll_rn(x * FPSCALE_F);
        atomicAdd(&wb[lab], (((unsigned long long)q) << CNT_BITS) + 1ull);
    }
}

__global__ void __launch_bounds__(256)
pass1_kernel(const float4* __restrict__ f, const int4* __restrict__ g,
             int scale, int pixPerBatch, int blocksPerBatch) {
    __shared__ unsigned long long wb[8][16];   // per-warp private bins
    int tid = threadIdx.x;
    int wid = tid >> 5;
    int batch = blockIdx.x / blocksPerBatch;
    int blk = blockIdx.x - batch * blocksPerBatch;

    if (tid < 128) ((unsigned long long*)wb)[tid] = 0ull;
    __syncthreads();

    unsigned long long* mywb = wb[wid];
    size_t base4 = ((size_t)batch * (size_t)pixPerBatch + (size_t)blk * 16384u) >> 2;

    for (int it = 0; it < 16; ++it) {
        size_t i = base4 + (size_t)(it * 256 + tid);
        float4 x = f[i];
        int4 gv = g[i];
        acc1(mywb, x.x, gv.x);
        acc1(mywb, x.y, gv.y);
        acc1(mywb, x.z, gv.z);
        acc1(mywb, x.w, gv.w);
    }
    __syncthreads();

    if (tid < 16) {
        unsigned long long t = 0ull;
#pragma unroll
        for (int w = 0; w < 8; ++w) t += wb[w][tid];
        if (t) atomicAdd(&g_bins1[scale * NSEG + batch * 17 + tid + 1], t);
    }
}

// ---------------------------------------------------------------------------
__global__ void mid_kernel() {
    int t = threadIdx.x;
    if (t < NSEG) {
        long long vs = 0, c = 0;
#pragma unroll
        for (int s = 0; s < 3; ++s) {
            long long raw = (long long)g_bins1[s * NSEG + t];
            long long cnt = raw & CNT_MASK;
            vs += (raw - cnt) >> CNT_BITS;
            c += cnt;
        }
        g_mean[t] = (c > 0) ? (float)((double)vs / (FPSCALE_D * (double)c)) : 0.0f;
    }
}

// ---------------------------------------------------------------------------
__device__ __forceinline__ void acc2(unsigned long long* wb, const float* ms,
                                     float x, int gv) {
    unsigned lab = (unsigned)(gv - 1);
    if (lab <= 15u) {
        float d = fabsf(x - ms[gv]) - 0.1f;
        d = fmaxf(d, 0.0f);
        long long q = __float2ll_rn(d * d * FPSCALE_F);
        atomicAdd(&wb[lab], (unsigned long long)q);
    }
}

__global__ void __launch_bounds__(256)
pass2_kernel(const float4* __restrict__ f, const int4* __restrict__ g,
             int scale, int pixPerBatch, int blocksPerBatch) {
    __shared__ unsigned long long wb[8][16];
    __shared__ float ms[17];
    int tid = threadIdx.x;
    int wid = tid >> 5;
    int batch = blockIdx.x / blocksPerBatch;
    int blk = blockIdx.x - batch * blocksPerBatch;

    if (tid < 128) ((unsigned long long*)wb)[tid] = 0ull;
    if (tid < 17) ms[tid] = g_mean[batch * 17 + tid];
    __syncthreads();

    unsigned long long* mywb = wb[wid];
    size_t base4 = ((size_t)batch * (size_t)pixPerBatch + (size_t)blk * 16384u) >> 2;

    for (int it = 0; it < 16; ++it) {
        size_t i = base4 + (size_t)(it * 256 + tid);
        float4 x = f[i];
        int4 gv = g[i];
        acc2(mywb, ms, x.x, gv.x);
        acc2(mywb, ms, x.y, gv.y);
        acc2(mywb, ms, x.z, gv.z);
        acc2(mywb, ms, x.w, gv.w);
    }
    __syncthreads();

    if (tid < 16) {
        unsigned long long t = 0ull;
#pragma unroll
        for (int w = 0; w < 8; ++w) t += wb[w][tid];
        if (t) atomicAdd(&g_bins2[scale * NSEG + batch * 17 + tid + 1], t);
    }
}

// ---------------------------------------------------------------------------
__global__ void __launch_bounds__(256) final_kernel(float* out) {
    __shared__ double s_pull[NSEG];
    __shared__ unsigned char s_pres[NSEG];
    __shared__ float s_mean[NSEG];
    __shared__ double redv[256];
    __shared__ int redn[256];

    int t = threadIdx.x;

    for (int sg = t; sg < NSEG; sg += 256) {
        long long totc = 0;
        double ps = 0.0;
#pragma unroll
        for (int s = 0; s < 3; ++s) {
            long long raw = (long long)g_bins1[s * NSEG + sg];
            long long cnt = raw & CNT_MASK;
            totc += cnt;
            if (cnt > 0) {
                double ssum = (double)(long long)g_bins2[s * NSEG + sg] / FPSCALE_D;
                ps += ssum / (double)cnt;
            }
        }
        bool inst = (sg % 17) != 0;
        bool pres = inst && (totc > 0);
        s_pres[sg] = (unsigned char)pres;
        s_pull[sg] = pres ? ps : 0.0;
        s_mean[sg] = g_mean[sg];
    }
    __syncthreads();

    // pull reduction
    double lv = 0.0;
    int ln = 0;
    for (int sg = t; sg < NSEG; sg += 256) {
        if (s_pres[sg]) { lv += s_pull[sg]; ln++; }
    }

    // push: thread t -> (batch b, instance i); ordered pairs (i,j), j != i
    double pv = 0.0;
    int pn = 0;
    {
        int b = t >> 4, i = t & 15;
        int segi = b * 17 + i + 1;
        if (s_pres[segi]) {
            float mi = s_mean[segi];
#pragma unroll
            for (int j = 0; j < 16; ++j) {
                if (j == i) continue;
                int segj = b * 17 + j + 1;
                if (s_pres[segj]) {
                    float d = fmaxf(3.0f - fabsf(mi - s_mean[segj]), 0.0f);
                    pv += (double)d * (double)d;
                    pn++;
                }
            }
        }
    }

    double pull_sum = 0.0;
    int n_pull = 0;
    redv[t] = lv; redn[t] = ln;
    __syncthreads();
    for (int s = 128; s > 0; s >>= 1) {
        if (t < s) { redv[t] += redv[t + s]; redn[t] += redn[t + s]; }
        __syncthreads();
    }
    if (t == 0) { pull_sum = redv[0]; n_pull = redn[0]; }
    __syncthreads();

    redv[t] = pv; redn[t] = pn;
    __syncthreads();
    for (int s = 128; s > 0; s >>= 1) {
        if (t < s) { redv[t] += redv[t + s]; redn[t] += redn[t + s]; }
        __syncthreads();
    }
    if (t == 0) {
        double push_sum = redv[0];
        int n_push = redn[0];
        double pull_loss = pull_sum / (double)(n_pull > 0 ? n_pull : 1);
        double push_loss = push_sum / (double)(n_push > 0 ? n_push : 1);
        out[0] = (float)(push_loss + pull_loss);
    }
}

// ---------------------------------------------------------------------------
extern "C" void kernel_launch(void* const* d_in, const int* in_sizes, int n_in,
                              void* d_out, int out_size) {
    const float* f[3];
    const int* g[3];

    // setup_inputs inserts featmap0, gt0, featmap1, gt1, featmap2, gt2
    // (interleaved). Detect layout defensively from sizes.
    if (n_in >= 6 && in_sizes[0] == in_sizes[1]) {
        f[0] = (const float*)d_in[0]; g[0] = (const int*)d_in[1];
        f[1] = (const float*)d_in[2]; g[1] = (const int*)d_in[3];
        f[2] = (const float*)d_in[4]; g[2] = (const int*)d_in[5];
    } else {
        f[0] = (const float*)d_in[0]; f[1] = (const float*)d_in[1];
        f[2] = (const float*)d_in[2];
        g[0] = (const int*)d_in[3]; g[1] = (const int*)d_in[4];
        g[2] = (const int*)d_in[5];
    }

    const int ppb[3] = {1024 * 1024, 512 * 512, 256 * 256};
    const int bpb[3] = {64, 16, 4};   // -> uniform 16384-pixel chunks per CTA

    zero_kernel<<<1, 3 * NSEG>>>();

    for (int s = 0; s < 3; ++s)
        pass1_kernel<<<16 * bpb[s], 256>>>((const float4*)f[s], (const int4*)g[s],
                                           s, ppb[s], bpb[s]);

    mid_kernel<<<1, 288>>>();

    for (int s = 0; s < 3; ++s)
        pass2_kernel<<<16 * bpb[s], 256>>>((const float4*)f[s], (const int4*)g[s],
                                           s, ppb[s], bpb[s]);

    final_kernel<<<1, 256>>>((float*)d_out);
}

// round 2
// speedup vs baseline: 3.0155x; 3.0155x over previous
#include <cuda_runtime.h>
#include <cstdint>

// MSPushPullLoss — round 2.
// Bottleneck last round: 1 shared-memory ATOMS per pixel (~50 cyc/warp-op at
// the MIO) => ~120us/pass. This version uses PER-THREAD private smem bins with
// plain LDS/IADD/STS (conflict-free banking: column index = tid), no atomics in
// the hot loop. Integer fixed-point accumulation -> bit-deterministic.

#define NSEG 272                  // 16 batches * 17 labels (0..16)
#define CNT_BITS 21
#define CNT_MASK ((1ll << CNT_BITS) - 1)
#define FPSCALE_F 16384.0f        // q14 fixed point
#define FPSCALE_D 16384.0

__device__ unsigned long long g_bins1[3 * NSEG];  // packed (sum_q14<<21 | count) per scale
__device__ unsigned long long g_bins2[3 * NSEG];  // pull sum_q14 per scale
__device__ float g_mean[NSEG];                    // pooled per-segment mean

// ---------------------------------------------------------------------------
__global__ void zero_kernel() {
    int t = threadIdx.x;
    if (t < 3 * NSEG) {
        g_bins1[t] = 0ull;
        g_bins2[t] = 0ull;
    }
}

// ---------------------------------------------------------------------------
// CTA -> (scale, batch, blk). 16384 pixels per CTA.
// scale0: 1024 CTAs (64/batch), scale1: 256 (16/batch), scale2: 64 (4/batch).
struct Map {
    const float4* f;
    const int4* g;
    int scale;
    size_t base4;   // float4 index of chunk start
    int batch;
};

__device__ __forceinline__ Map decode(const float* f0, const float* f1, const float* f2,
                                      const int* g0, const int* g1, const int* g2) {
    Map m;
    int cid = blockIdx.x;
    if (cid < 1024) {
        m.scale = 0; m.f = (const float4*)f0; m.g = (const int4*)g0;
        m.batch = cid >> 6;
        m.base4 = (size_t)m.batch * (1u << 18) + (size_t)(cid & 63) * 4096u;
    } else if (cid < 1280) {
        int c = cid - 1024;
        m.scale = 1; m.f = (const float4*)f1; m.g = (const int4*)g1;
        m.batch = c >> 4;
        m.base4 = (size_t)m.batch * (1u << 16) + (size_t)(c & 15) * 4096u;
    } else {
        int c = cid - 1280;
        m.scale = 2; m.f = (const float4*)f2; m.g = (const int4*)g2;
        m.batch = c >> 2;
        m.base4 = (size_t)m.batch * (1u << 14) + (size_t)(c & 3) * 4096u;
    }
    return m;
}

// ---------------------------------------------------------------------------
// Pass 1: per-(b,label) sum & count. Per-thread bins: bins[row][tid], row =
// label-1 (row 16 = invalid dump). Packed i32: (q14 << 7) + 1, <=64 px/thread.
__global__ void __launch_bounds__(256)
pass1_kernel(const float* __restrict__ f0, const float* __restrict__ f1,
             const float* __restrict__ f2, const int* __restrict__ g0,
             const int* __restrict__ g1, const int* __restrict__ g2) {
    __shared__ int bins[17][256];
    int tid = threadIdx.x;
    Map m = decode(f0, f1, f2, g0, g1, g2);

#pragma unroll
    for (int r = 0; r < 17; ++r) bins[r][tid] = 0;
    __syncthreads();

    int* mybin = &bins[0][tid];          // stride 256 ints between rows

    for (int it = 0; it < 16; ++it) {
        size_t i = m.base4 + (size_t)(it * 256 + tid);
        float4 x = m.f[i];
        int4 gv = m.g[i];
#pragma unroll
        for (int p = 0; p < 4; ++p) {
            float xv = (p == 0) ? x.x : (p == 1) ? x.y : (p == 2) ? x.z : x.w;
            int gg = (p == 0) ? gv.x : (p == 1) ? gv.y : (p == 2) ? gv.z : gv.w;
            unsigned row = min((unsigned)(gg - 1), 16u);
            int q = __float2int_rn(xv * FPSCALE_F);
            mybin[row << 8] += (q << 7) + 1;
        }
    }
    __syncthreads();

    // epilogue: warp w reduces rows 2w, 2w+1 (rows 0..15 = labels 1..16)
    int w = tid >> 5, lane = tid & 31;
#pragma unroll
    for (int rr = 0; rr < 2; ++rr) {
        int row = 2 * w + rr;
        long long sq = 0;
        int sc = 0;
#pragma unroll
        for (int k = 0; k < 8; ++k) {
            int v = bins[row][lane + 32 * k];
            int c = v & 127;
            sc += c;
            sq += (long long)((v - c) >> 7);
        }
#pragma unroll
        for (int off = 16; off > 0; off >>= 1) {
            sq += __shfl_down_sync(0xffffffffu, sq, off);
            sc += __shfl_down_sync(0xffffffffu, sc, off);
        }
        if (lane == 0 && (sc | sq))
            atomicAdd(&g_bins1[m.scale * NSEG + m.batch * 17 + row + 1],
                      (((unsigned long long)(long long)sq) << CNT_BITS) +
                          (unsigned long long)sc);
    }
}

// ---------------------------------------------------------------------------
__global__ void mid_kernel() {
    int t = threadIdx.x;
    if (t < NSEG) {
        long long vs = 0, c = 0;
#pragma unroll
        for (int s = 0; s < 3; ++s) {
            long long raw = (long long)g_bins1[s * NSEG + t];
            long long cnt = raw & CNT_MASK;
            vs += (raw - cnt) >> CNT_BITS;
            c += cnt;
        }
        g_mean[t] = (c > 0) ? (float)((double)vs / (FPSCALE_D * (double)c)) : 0.0f;
    }
}

// ---------------------------------------------------------------------------
// Pass 2: pull sums. bins accumulate plain non-negative q14 values.
__global__ void __launch_bounds__(256)
pass2_kernel(const float* __restrict__ f0, const float* __restrict__ f1,
             const float* __restrict__ f2, const int* __restrict__ g0,
             const int* __restrict__ g1, const int* __restrict__ g2) {
    __shared__ int bins[17][256];
    __shared__ float msr[17];            // msr[row] = mean of label row+1; msr[16]=0
    int tid = threadIdx.x;
    Map m = decode(f0, f1, f2, g0, g1, g2);

#pragma unroll
    for (int r = 0; r < 17; ++r) bins[r][tid] = 0;
    if (tid < 16) msr[tid] = g_mean[m.batch * 17 + tid + 1];
    if (tid == 16) msr[16] = 0.0f;
    __syncthreads();

    int* mybin = &bins[0][tid];

    for (int it = 0; it < 16; ++it) {
        size_t i = m.base4 + (size_t)(it * 256 + tid);
        float4 x = m.f[i];
        int4 gv = m.g[i];
#pragma unroll
        for (int p = 0; p < 4; ++p) {
            float xv = (p == 0) ? x.x : (p == 1) ? x.y : (p == 2) ? x.z : x.w;
            int gg = (p == 0) ? gv.x : (p == 1) ? gv.y : (p == 2) ? gv.z : gv.w;
            unsigned row = min((unsigned)(gg - 1), 16u);
            float d = fmaxf(fabsf(xv - msr[row]) - 0.1f, 0.0f);
            int q = __float2int_rn(d * d * FPSCALE_F);
            mybin[row << 8] += q;
        }
    }
    __syncthreads();

    int w = tid >> 5, lane = tid & 31;
#pragma unroll
    for (int rr = 0; rr < 2; ++rr) {
        int row = 2 * w + rr;
        long long sq = 0;
#pragma unroll
        for (int k = 0; k < 8; ++k) sq += (long long)bins[row][lane + 32 * k];
#pragma unroll
        for (int off = 16; off > 0; off >>= 1)
            sq += __shfl_down_sync(0xffffffffu, sq, off);
        if (lane == 0 && sq)
            atomicAdd(&g_bins2[m.scale * NSEG + m.batch * 17 + row + 1],
                      (unsigned long long)sq);
    }
}

// ---------------------------------------------------------------------------
__global__ void __launch_bounds__(256) final_kernel(float* out) {
    __shared__ double s_pull[NSEG];
    __shared__ unsigned char s_pres[NSEG];
    __shared__ float s_mean[NSEG];
    __shared__ double redv[256];
    __shared__ int redn[256];

    int t = threadIdx.x;

    for (int sg = t; sg < NSEG; sg += 256) {
        long long totc = 0;
        double ps = 0.0;
#pragma unroll
        for (int s = 0; s < 3; ++s) {
            long long raw = (long long)g_bins1[s * NSEG + sg];
            long long cnt = raw & CNT_MASK;
            totc += cnt;
            if (cnt > 0) {
                double ssum = (double)(long long)g_bins2[s * NSEG + sg] / FPSCALE_D;
                ps += ssum / (double)cnt;
            }
        }
        bool inst = (sg % 17) != 0;
        bool pres = inst && (totc > 0);
        s_pres[sg] = (unsigned char)pres;
        s_pull[sg] = pres ? ps : 0.0;
        s_mean[sg] = g_mean[sg];
    }
    __syncthreads();

    double lv = 0.0;
    int ln = 0;
    for (int sg = t; sg < NSEG; sg += 256) {
        if (s_pres[sg]) { lv += s_pull[sg]; ln++; }
    }

    double pv = 0.0;
    int pn = 0;
    {
        int b = t >> 4, i = t & 15;
        int segi = b * 17 + i + 1;
        if (s_pres[segi]) {
            float mi = s_mean[segi];
#pragma unroll
            for (int j = 0; j < 16; ++j) {
                if (j == i) continue;
                int segj = b * 17 + j + 1;
                if (s_pres[segj]) {
                    float d = fmaxf(3.0f - fabsf(mi - s_mean[segj]), 0.0f);
                    pv += (double)d * (double)d;
                    pn++;
                }
            }
        }
    }

    double pull_sum = 0.0;
    int n_pull = 0;
    redv[t] = lv; redn[t] = ln;
    __syncthreads();
    for (int s = 128; s > 0; s >>= 1) {
        if (t < s) { redv[t] += redv[t + s]; redn[t] += redn[t + s]; }
        __syncthreads();
    }
    if (t == 0) { pull_sum = redv[0]; n_pull = redn[0]; }
    __syncthreads();

    redv[t] = pv; redn[t] = pn;
    __syncthreads();
    for (int s = 128; s > 0; s >>= 1) {
        if (t < s) { redv[t] += redv[t + s]; redn[t] += redn[t + s]; }
        __syncthreads();
    }
    if (t == 0) {
        double push_sum = redv[0];
        int n_push = redn[0];
        double pull_loss = pull_sum / (double)(n_pull > 0 ? n_pull : 1);
        double push_loss = push_sum / (double)(n_push > 0 ? n_push : 1);
        out[0] = (float)(push_loss + pull_loss);
    }
}

// ---------------------------------------------------------------------------
extern "C" void kernel_launch(void* const* d_in, const int* in_sizes, int n_in,
                              void* d_out, int out_size) {
    const float* f[3];
    const int* g[3];

    if (n_in >= 6 && in_sizes[0] == in_sizes[1]) {       // interleaved f,g pairs
        f[0] = (const float*)d_in[0]; g[0] = (const int*)d_in[1];
        f[1] = (const float*)d_in[2]; g[1] = (const int*)d_in[3];
        f[2] = (const float*)d_in[4]; g[2] = (const int*)d_in[5];
    } else {                                              // grouped
        f[0] = (const float*)d_in[0]; f[1] = (const float*)d_in[1];
        f[2] = (const float*)d_in[2];
        g[0] = (const int*)d_in[3]; g[1] = (const int*)d_in[4];
        g[2] = (const int*)d_in[5];
    }

    const int NCTA = 1024 + 256 + 64;   // 16384 pixels per CTA across 3 scales

    zero_kernel<<<1, 3 * NSEG>>>();
    pass1_kernel<<<NCTA, 256>>>(f[0], f[1], f[2], g[0], g[1], g[2]);
    mid_kernel<<<1, 288>>>();
    pass2_kernel<<<NCTA, 256>>>(f[0], f[1], f[2], g[0], g[1], g[2]);
    final_kernel<<<1, 256>>>((float*)d_out);
}

// round 4
// speedup vs baseline: 3.4450x; 1.1424x over previous
#include <cuda_runtime.h>
#include <cstdint>

// MSPushPullLoss — round 4 (re-bench of round-3 design; round 3 hit an infra
// container failure and was never executed).
// DRAM-stream bound (4.76 TB/s measured in round 2). Design:
//  * pass2 walks each chunk in REVERSE so it re-reads what pass1 left in L2
//  * 16 px/thread/iter (8 front-batched LDG.128) for deep MLP
//  * 2 launches total: mean-compute fused into pass1 tail CTA, final loss +
//    state re-zeroing fused into pass2 tail CTA (deterministic across graph
//    replays: consumer re-zeroes everything it read).

#define NSEG 272                  // 16 batches * 17 labels (0..16)
#define CNT_BITS 21
#define CNT_MASK ((1ll << CNT_BITS) - 1)
#define FPSCALE_F 16384.0f        // q14 fixed point
#define FPSCALE_D 16384.0
#define NCTA (1024 + 256 + 64)

__device__ unsigned long long g_bins1[3 * NSEG];  // packed (sum_q14<<21 | count)
__device__ unsigned long long g_bins2[3 * NSEG];  // pull sum_q14
__device__ float g_mean[NSEG];
__device__ int g_cnt1;            // tail-CTA election counters (self-resetting)
__device__ int g_cnt2;

// ---------------------------------------------------------------------------
struct Map {
    const float4* f;
    const int4* g;
    int scale;
    size_t base4;   // float4 index of 4096-float4 chunk start
    int batch;
};

__device__ __forceinline__ Map decode(const float* f0, const float* f1, const float* f2,
                                      const int* g0, const int* g1, const int* g2) {
    Map m;
    int cid = blockIdx.x;
    if (cid < 1024) {
        m.scale = 0; m.f = (const float4*)f0; m.g = (const int4*)g0;
        m.batch = cid >> 6;
        m.base4 = (size_t)m.batch * (1u << 18) + (size_t)(cid & 63) * 4096u;
    } else if (cid < 1280) {
        int c = cid - 1024;
        m.scale = 1; m.f = (const float4*)f1; m.g = (const int4*)g1;
        m.batch = c >> 4;
        m.base4 = (size_t)m.batch * (1u << 16) + (size_t)(c & 15) * 4096u;
    } else {
        int c = cid - 1280;
        m.scale = 2; m.f = (const float4*)f2; m.g = (const int4*)g2;
        m.batch = c >> 2;
        m.base4 = (size_t)m.batch * (1u << 14) + (size_t)(c & 3) * 4096u;
    }
    return m;
}

// ---------------------------------------------------------------------------
__device__ __forceinline__ void acc1px(int* mybin, float xv, int gg) {
    unsigned row = min((unsigned)(gg - 1), 16u);   // row 16 = invalid dump
    int q = __float2int_rn(xv * FPSCALE_F);
    mybin[row << 8] += q * 128 + 1;                // (q<<7) | count
}

__device__ __forceinline__ void acc1v(int* mybin, float4 x, int4 g) {
    acc1px(mybin, x.x, g.x); acc1px(mybin, x.y, g.y);
    acc1px(mybin, x.z, g.z); acc1px(mybin, x.w, g.w);
}

__global__ void __launch_bounds__(256)
pass1_kernel(const float* __restrict__ f0, const float* __restrict__ f1,
             const float* __restrict__ f2, const int* __restrict__ g0,
             const int* __restrict__ g1, const int* __restrict__ g2) {
    __shared__ int bins[17][256];
    __shared__ int isLast;
    int tid = threadIdx.x;
    Map m = decode(f0, f1, f2, g0, g1, g2);

#pragma unroll
    for (int r = 0; r < 17; ++r) bins[r][tid] = 0;
    __syncthreads();

    int* mybin = &bins[0][tid];

#pragma unroll
    for (int it = 0; it < 4; ++it) {
        size_t i0 = m.base4 + (size_t)(it * 1024 + tid);
        float4 xa = m.f[i0];        float4 xb = m.f[i0 + 256];
        float4 xc = m.f[i0 + 512];  float4 xd = m.f[i0 + 768];
        int4 ga = m.g[i0];          int4 gb = m.g[i0 + 256];
        int4 gc = m.g[i0 + 512];    int4 gd = m.g[i0 + 768];
        acc1v(mybin, xa, ga); acc1v(mybin, xb, gb);
        acc1v(mybin, xc, gc); acc1v(mybin, xd, gd);
    }
    __syncthreads();

    // warp w reduces rows 2w, 2w+1 (rows 0..15 = labels 1..16)
    int w = tid >> 5, lane = tid & 31;
#pragma unroll
    for (int rr = 0; rr < 2; ++rr) {
        int row = 2 * w + rr;
        long long sq = 0;
        int sc = 0;
#pragma unroll
        for (int k = 0; k < 8; ++k) {
            int v = bins[row][lane + 32 * k];
            int c = v & 127;
            sc += c;
            sq += (long long)((v - c) >> 7);
        }
#pragma unroll
        for (int off = 16; off > 0; off >>= 1) {
            sq += __shfl_down_sync(0xffffffffu, sq, off);
            sc += __shfl_down_sync(0xffffffffu, sc, off);
        }
        if (lane == 0 && (sc | sq))
            atomicAdd(&g_bins1[m.scale * NSEG + m.batch * 17 + row + 1],
                      (((unsigned long long)(long long)sq) << CNT_BITS) +
                          (unsigned long long)sc);
    }

    // tail-CTA computes pooled means (release/acquire via threadfence+atomic)
    if (tid == 0) {
        __threadfence();
        isLast = (atomicAdd(&g_cnt1, 1) == NCTA - 1) ? 1 : 0;
    }
    __syncthreads();
    if (isLast) {
        if (tid == 0) g_cnt1 = 0;          // reset for next graph replay
        __threadfence();
        for (int sg = tid; sg < NSEG; sg += 256) {
            long long vs = 0, c = 0;
#pragma unroll
            for (int s = 0; s < 3; ++s) {
                long long raw = (long long)g_bins1[s * NSEG + sg];
                long long cnt = raw & CNT_MASK;
                vs += (raw - cnt) >> CNT_BITS;
                c += cnt;
            }
            g_mean[sg] = (c > 0) ? (float)((double)vs / (FPSCALE_D * (double)c)) : 0.0f;
        }
    }
}

// ---------------------------------------------------------------------------
__device__ __forceinline__ void acc2px(int* mybin, const float* msr, float xv, int gg) {
    unsigned row = min((unsigned)(gg - 1), 16u);
    float d = fmaxf(fabsf(xv - msr[row]) - 0.1f, 0.0f);
    mybin[row << 8] += __float2int_rn(d * d * FPSCALE_F);
}

__device__ __forceinline__ void acc2v(int* mybin, const float* msr, float4 x, int4 g) {
    acc2px(mybin, msr, x.x, g.x); acc2px(mybin, msr, x.y, g.y);
    acc2px(mybin, msr, x.z, g.z); acc2px(mybin, msr, x.w, g.w);
}

__global__ void __launch_bounds__(256)
pass2_kernel(const float* __restrict__ f0, const float* __restrict__ f1,
             const float* __restrict__ f2, const int* __restrict__ g0,
             const int* __restrict__ g1, const int* __restrict__ g2,
             float* __restrict__ out) {
    __shared__ int bins[17][256];
    __shared__ float msr[17];
    __shared__ int isLast;
    int tid = threadIdx.x;
    Map m = decode(f0, f1, f2, g0, g1, g2);

#pragma unroll
    for (int r = 0; r < 17; ++r) bins[r][tid] = 0;
    if (tid < 16) msr[tid] = g_mean[m.batch * 17 + tid + 1];
    if (tid == 16) msr[16] = 0.0f;
    __syncthreads();

    int* mybin = &bins[0][tid];

    // REVERSE walk: re-read what pass1 most recently left in L2.
#pragma unroll
    for (int it = 3; it >= 0; --it) {
        size_t i0 = m.base4 + (size_t)(it * 1024 + tid);
        float4 xa = m.f[i0];        float4 xb = m.f[i0 + 256];
        float4 xc = m.f[i0 + 512];  float4 xd = m.f[i0 + 768];
        int4 ga = m.g[i0];          int4 gb = m.g[i0 + 256];
        int4 gc = m.g[i0 + 512];    int4 gd = m.g[i0 + 768];
        acc2v(mybin, msr, xd, gd); acc2v(mybin, msr, xc, gc);
        acc2v(mybin, msr, xb, gb); acc2v(mybin, msr, xa, ga);
    }
    __syncthreads();

    int w = tid >> 5, lane = tid & 31;
#pragma unroll
    for (int rr = 0; rr < 2; ++rr) {
        int row = 2 * w + rr;
        long long sq = 0;
#pragma unroll
        for (int k = 0; k < 8; ++k) sq += (long long)bins[row][lane + 32 * k];
#pragma unroll
        for (int off = 16; off > 0; off >>= 1)
            sq += __shfl_down_sync(0xffffffffu, sq, off);
        if (lane == 0 && sq)
            atomicAdd(&g_bins2[m.scale * NSEG + m.batch * 17 + row + 1],
                      (unsigned long long)sq);
    }

    // tail-CTA: final loss + self-clean all global state
    if (tid == 0) {
        __threadfence();
        isLast = (atomicAdd(&g_cnt2, 1) == NCTA - 1) ? 1 : 0;
    }
    __syncthreads();
    if (!isLast) return;
    if (tid == 0) g_cnt2 = 0;
    __threadfence();

    __shared__ double s_pull[NSEG];
    __shared__ unsigned char s_pres[NSEG];
    __shared__ float s_mean[NSEG];
    __shared__ double redv[256];
    __shared__ int redn[256];

    for (int sg = tid; sg < NSEG; sg += 256) {
        long long totc = 0;
        double ps = 0.0;
#pragma unroll
        for (int s = 0; s < 3; ++s) {
            long long raw = (long long)g_bins1[s * NSEG + sg];
            long long cnt = raw & CNT_MASK;
            totc += cnt;
            if (cnt > 0) {
                double ssum = (double)(long long)g_bins2[s * NSEG + sg] / FPSCALE_D;
                ps += ssum / (double)cnt;
            }
        }
        bool inst = (sg % 17) != 0;
        bool pres = inst && (totc > 0);
        s_pres[sg] = (unsigned char)pres;
        s_pull[sg] = pres ? ps : 0.0;
        s_mean[sg] = g_mean[sg];
    }
    __syncthreads();

    double lv = 0.0;
    int ln = 0;
    for (int sg = tid; sg < NSEG; sg += 256)
        if (s_pres[sg]) { lv += s_pull[sg]; ln++; }

    double pv = 0.0;
    int pn = 0;
    {
        int b = tid >> 4, i = tid & 15;
        int segi = b * 17 + i + 1;
        if (s_pres[segi]) {
            float mi = s_mean[segi];
#pragma unroll
            for (int j = 0; j < 16; ++j) {
                if (j == i) continue;
                int segj = b * 17 + j + 1;
                if (s_pres[segj]) {
                    float d = fmaxf(3.0f - fabsf(mi - s_mean[segj]), 0.0f);
                    pv += (double)d * (double)d;
                    pn++;
                }
            }
        }
    }

    double pull_sum = 0.0;
    int n_pull = 0;
    redv[tid] = lv; redn[tid] = ln;
    __syncthreads();
    for (int s = 128; s > 0; s >>= 1) {
        if (tid < s) { redv[tid] += redv[tid + s]; redn[tid] += redn[tid + s]; }
        __syncthreads();
    }
    if (tid == 0) { pull_sum = redv[0]; n_pull = redn[0]; }
    __syncthreads();

    redv[tid] = pv; redn[tid] = pn;
    __syncthreads();
    for (int s = 128; s > 0; s >>= 1) {
        if (tid < s) { redv[tid] += redv[tid + s]; redn[tid] += redn[tid + s]; }
        __syncthreads();
    }
    if (tid == 0) {
        double push_sum = redv[0];
        int n_push = redn[0];
        double pull_loss = pull_sum / (double)(n_pull > 0 ? n_pull : 1);
        double push_loss = push_sum / (double)(n_push > 0 ? n_push : 1);
        out[0] = (float)(push_loss + pull_loss);
    }
    __syncthreads();
    // self-clean for next graph replay (after all reads above)
    for (int t = tid; t < 3 * NSEG; t += 256) {
        g_bins1[t] = 0ull;
        g_bins2[t] = 0ull;
    }
}

// ---------------------------------------------------------------------------
extern "C" void kernel_launch(void* const* d_in, const int* in_sizes, int n_in,
                              void* d_out, int out_size) {
    const float* f[3];
    const int* g[3];

    if (n_in >= 6 && in_sizes[0] == in_sizes[1]) {       // interleaved f,g pairs
        f[0] = (const float*)d_in[0]; g[0] = (const int*)d_in[1];
        f[1] = (const float*)d_in[2]; g[1] = (const int*)d_in[3];
        f[2] = (const float*)d_in[4]; g[2] = (const int*)d_in[5];
    } else {                                              // grouped
        f[0] = (const float*)d_in[0]; f[1] = (const float*)d_in[1];
        f[2] = (const float*)d_in[2];
        g[0] = (const int*)d_in[3]; g[1] = (const int*)d_in[4];
        g[2] = (const int*)d_in[5];
    }

    pass1_kernel<<<NCTA, 256>>>(f[0], f[1], f[2], g[0], g[1], g[2]);
    pass2_kernel<<<NCTA, 256>>>(f[0], f[1], f[2], g[0], g[1], g[2], (float*)d_out);
}